// round 14
// baseline (speedup 1.0000x reference)
#include <cuda_runtime.h>
#include <cuda_fp16.h>
#include <math_constants.h>

#define MAXN 100000
#define MAXE 720000
#define NH   8
#define HC   128

__device__ __half g_xwh[MAXN * HC];   // x @ W, fp16 for gather  [N, H*C]
__device__ float  g_atgt[MAXN * NH];
__device__ float  g_asrc[MAXN * NH];
__device__ float  g_wt[HC * HC];      // W^T, tf32-rounded bits, [n][k]
__device__ int    g_deg[MAXN];
__device__ int    g_start[MAXN];      // exclusive prefix; after permute = end
__device__ int    g_srcidx[MAXE];
__device__ int    g_is64;

__device__ __forceinline__ unsigned cvt_tf32(float f) {
    unsigned r;
    asm("cvt.rna.tf32.f32 %0, %1;" : "=r"(r) : "f"(f));
    return r;
}

__device__ __forceinline__ int edge_at(const int* ei32, int idx, int shift) {
    return ei32[idx << shift];
}

// ---------------------------------------------------------------------------
// K_prepW (main stream): W^T tf32 precompute — feeds the GEMM.
// ---------------------------------------------------------------------------
__global__ void k_prep_w(const float* __restrict__ w) {
    int i = blockIdx.x * blockDim.x + threadIdx.x;   // 16384 threads
    int k = i >> 7, nn = i & 127;
    g_wt[nn * HC + k] = __uint_as_float(cvt_tf32(w[i]));
}

// ---------------------------------------------------------------------------
// K_prepE (stream 2): zero degrees + detect edge dtype — feeds hist.
// ---------------------------------------------------------------------------
__global__ void k_prep_e(const int* __restrict__ ei32, int n, int E) {
    int i = blockIdx.x * blockDim.x + threadIdx.x;
    if (i < n) g_deg[i] = 0;
    if (i == 0) {
        int m = E < 128 ? E : 128;
        int nz = 0;
        for (int j = 0; j < m; j++) nz |= ei32[2 * j + 1];
        g_is64 = (nz == 0) ? 1 : 0;
    }
}

// ---------------------------------------------------------------------------
// K1: tf32 tensor-core GEMM xw = x @ W (128x128 tile/block) + fused att dots.
// (R10 proven version — 64 accumulators/thread, no spills.)
// ---------------------------------------------------------------------------
#define SA_STRIDE 132
__global__ void __launch_bounds__(256) k_gemm_tf32(
        const float* __restrict__ x, const float* __restrict__ att, int n) {
    extern __shared__ float smem[];
    float* sA   = smem;
    float* sB   = smem + 128 * SA_STRIDE;
    float* sAtt = smem + 2 * 128 * SA_STRIDE;

    int tid  = threadIdx.x;
    int lane = tid & 31, warp = tid >> 5;
    int g = lane >> 2, t = lane & 3;
    int row0g = blockIdx.x * 128;

    sAtt[tid] = att[tid];

    const float4* wt4 = (const float4*)g_wt;
#pragma unroll
    for (int i = 0; i < 16; i++) {
        int idx = tid + i * 256;
        int nn = idx >> 5, k4 = (idx & 31) * 4;
        *(float4*)(sB + nn * SA_STRIDE + k4) = wt4[idx];
    }

    const float4* x4 = (const float4*)(x + (size_t)row0g * 128);
#pragma unroll
    for (int i = 0; i < 16; i++) {
        int idx = tid + i * 256;
        int r  = idx >> 5;
        int c4 = (idx & 31) * 4;
        float4 v = (row0g + r < n) ? x4[idx] : make_float4(0.f, 0.f, 0.f, 0.f);
        float4 c;
        c.x = __uint_as_float(cvt_tf32(v.x));
        c.y = __uint_as_float(cvt_tf32(v.y));
        c.z = __uint_as_float(cvt_tf32(v.z));
        c.w = __uint_as_float(cvt_tf32(v.w));
        *(float4*)(sA + r * SA_STRIDE + c4) = c;
    }
    __syncthreads();

    int rbase = warp * 16;
    const float* pa0 = sA + (rbase + g) * SA_STRIDE;
    const float* pa1 = sA + (rbase + g + 8) * SA_STRIDE;

    float acc[16][4];
#pragma unroll
    for (int nt = 0; nt < 16; nt++)
#pragma unroll
        for (int j = 0; j < 4; j++) acc[nt][j] = 0.f;

#pragma unroll
    for (int kt = 0; kt < 16; kt++) {
        int k0 = kt * 8;
        unsigned a0 = __float_as_uint(pa0[k0 + t]);
        unsigned a1 = __float_as_uint(pa1[k0 + t]);
        unsigned a2 = __float_as_uint(pa0[k0 + t + 4]);
        unsigned a3 = __float_as_uint(pa1[k0 + t + 4]);
#pragma unroll
        for (int nt = 0; nt < 16; nt++) {
            const float* pb = sB + (nt * 8 + g) * SA_STRIDE + k0;
            unsigned b0 = __float_as_uint(pb[t]);
            unsigned b1 = __float_as_uint(pb[t + 4]);
            asm volatile(
                "mma.sync.aligned.m16n8k8.row.col.f32.tf32.tf32.f32 "
                "{%0,%1,%2,%3}, {%4,%5,%6,%7}, {%8,%9}, {%0,%1,%2,%3};"
                : "+f"(acc[nt][0]), "+f"(acc[nt][1]), "+f"(acc[nt][2]), "+f"(acc[nt][3])
                : "r"(a0), "r"(a1), "r"(a2), "r"(a3), "r"(b0), "r"(b1));
        }
    }

    int row0 = row0g + rbase + g;
    int row1 = row0 + 8;
#pragma unroll
    for (int nt = 0; nt < 16; nt++) {
        int col = nt * 8 + 2 * t;
        if (row0 < n)
            *(__half2*)(g_xwh + (size_t)row0 * 128 + col) = __floats2half2_rn(acc[nt][0], acc[nt][1]);
        if (row1 < n)
            *(__half2*)(g_xwh + (size_t)row1 * 128 + col) = __floats2half2_rn(acc[nt][2], acc[nt][3]);
    }

#pragma unroll
    for (int h = 0; h < NH; h++) {
        float dt0 = 0.f, ds0 = 0.f, dt1 = 0.f, ds1 = 0.f;
#pragma unroll
        for (int j = 0; j < 2; j++) {
            int nt = 2 * h + j;
            int cw = j * 8 + 2 * t;
            float at0 = sAtt[h * 32 + cw],      at1 = sAtt[h * 32 + cw + 1];
            float as0 = sAtt[h * 32 + 16 + cw], as1 = sAtt[h * 32 + 16 + cw + 1];
            dt0 += acc[nt][0] * at0 + acc[nt][1] * at1;
            ds0 += acc[nt][0] * as0 + acc[nt][1] * as1;
            dt1 += acc[nt][2] * at0 + acc[nt][3] * at1;
            ds1 += acc[nt][2] * as0 + acc[nt][3] * as1;
        }
        dt0 += __shfl_xor_sync(0xffffffff, dt0, 1); dt0 += __shfl_xor_sync(0xffffffff, dt0, 2);
        ds0 += __shfl_xor_sync(0xffffffff, ds0, 1); ds0 += __shfl_xor_sync(0xffffffff, ds0, 2);
        dt1 += __shfl_xor_sync(0xffffffff, dt1, 1); dt1 += __shfl_xor_sync(0xffffffff, dt1, 2);
        ds1 += __shfl_xor_sync(0xffffffff, ds1, 1); ds1 += __shfl_xor_sync(0xffffffff, ds1, 2);
        if (t == 0) {
            if (row0 < n) { g_atgt[row0 * NH + h] = dt0; g_asrc[row0 * NH + h] = ds0; }
            if (row1 < n) { g_atgt[row1 * NH + h] = dt1; g_asrc[row1 * NH + h] = ds1; }
        }
    }
}

// ---------------------------------------------------------------------------
// CSR build
// ---------------------------------------------------------------------------
__global__ void k_hist(const int* __restrict__ ei32, int E) {
    int i = blockIdx.x * blockDim.x + threadIdx.x;
    if (i >= E) return;
    int d = edge_at(ei32, E + i, g_is64);
    atomicAdd(&g_deg[d], 1);
}

// Single-block exclusive scan of g_deg -> g_start (n up to MAXN).
__global__ void __launch_bounds__(1024) k_scan_all(int n) {
    int t = threadIdx.x;
    int per = (((n + 1023) >> 10) + 3) & ~3;     // per-thread span, multiple of 4
    int lo = t * per;
    int hi = lo + per; if (hi > n) hi = n;
    if (lo > n) lo = n;

    int sum = 0;
    int i = lo;
    for (; i + 3 < hi; i += 4) {
        int4 v = *(const int4*)(g_deg + i);
        sum += v.x + v.y + v.z + v.w;
    }
    for (; i < hi; i++) sum += g_deg[i];

    int lane = t & 31, w = t >> 5;
    int x = sum;
#pragma unroll
    for (int o = 1; o < 32; o <<= 1) {
        int y = __shfl_up_sync(0xffffffff, x, o);
        if (lane >= o) x += y;
    }
    __shared__ int wsum[32];
    if (lane == 31) wsum[w] = x;
    __syncthreads();
    if (t < 32) {
        int s = wsum[t];
#pragma unroll
        for (int o = 1; o < 32; o <<= 1) {
            int y = __shfl_up_sync(0xffffffff, s, o);
            if (t >= o) s += y;
        }
        wsum[t] = s;
    }
    __syncthreads();
    int ex = x - sum + ((w > 0) ? wsum[w - 1] : 0);

    for (i = lo; i < hi; i++) {
        g_start[i] = ex;
        ex += g_deg[i];
    }
}

__global__ void k_permute(const int* __restrict__ ei32, int E) {
    int i = blockIdx.x * blockDim.x + threadIdx.x;
    if (i >= E) return;
    int sh = g_is64;
    int s = edge_at(ei32, i, sh);
    int d = edge_at(ei32, E + i, sh);
    int pos = atomicAdd(&g_start[d], 1);   // g_start becomes end-of-bucket
    g_srcidx[pos] = s;
}

// ---------------------------------------------------------------------------
// K5: gather — one warp per dst node, software-pipelined, fp16 xw.
// ---------------------------------------------------------------------------
__global__ void __launch_bounds__(256) k_gather(float* __restrict__ out,
                                                const float* __restrict__ bias, int n) {
    int gw = (blockIdx.x * blockDim.x + threadIdx.x) >> 5;
    if (gw >= n) return;
    int lane = threadIdx.x & 31;
    int d = gw;
    int h = lane >> 2;
    float atgtv = g_atgt[d * NH + h];
    int deg = g_deg[d];
    int start = g_start[d] - deg;          // g_start holds end after permute
    float4 acc = make_float4(0.f, 0.f, 0.f, 0.f);
    float den = 0.f;
    const uint2* xw2 = (const uint2*)g_xwh;

    if (deg > 0) {
        int s_n = g_srcidx[start];
        float as_n = g_asrc[s_n * NH + h];
        uint2 v_n = __ldg(xw2 + (size_t)s_n * 32 + lane);
        for (int j = 0; j < deg; j++) {
            float as = as_n;
            uint2 vr = v_n;
            if (j + 1 < deg) {
                int s2 = g_srcidx[start + j + 1];
                as_n = g_asrc[s2 * NH + h];
                v_n = __ldg(xw2 + (size_t)s2 * 32 + lane);
            }
            float a = atgtv + as;
            a = a > 0.f ? a : 0.2f * a;
            float ex = __expf(a);
            float2 lo = __half22float2(*(__half2*)&vr.x);
            float2 hi = __half22float2(*(__half2*)&vr.y);
            acc.x += ex * lo.x; acc.y += ex * lo.y;
            acc.z += ex * hi.x; acc.w += ex * hi.y;
            den += ex;
        }
    }
    float inv = (den > 0.f) ? 1.f / den : 0.f;
    float4 b = ((const float4*)bias)[lane];
    float4 o;
    o.x = acc.x * inv + b.x; o.y = acc.y * inv + b.y;
    o.z = acc.z * inv + b.z; o.w = acc.w * inv + b.w;
    ((float4*)out)[(size_t)d * 32 + lane] = o;
}

// ---------------------------------------------------------------------------
extern "C" void kernel_launch(void* const* d_in, const int* in_sizes, int n_in,
                              void* d_out, int out_size) {
    int order[16];
    for (int i = 0; i < n_in; i++) order[i] = i;
    for (int a = 0; a < n_in; a++)
        for (int b = a + 1; b < n_in; b++)
            if (in_sizes[order[b]] > in_sizes[order[a]]) {
                int t = order[a]; order[a] = order[b]; order[b] = t;
            }
    const float* x    = (const float*)d_in[order[0]];
    const int*   ei32 = (const int*)  d_in[order[1]];
    const float* w    = (const float*)d_in[order[3]];
    const float* att  = (const float*)d_in[order[4]];
    const float* bias = (const float*)d_in[order[5]];
    float*       out  = (float*)d_out;

    int n = in_sizes[order[0]] / 128;
    int E = in_sizes[order[1]] / 2;

    static cudaStream_t s2 = nullptr;
    static cudaEvent_t evFork = nullptr, evJoin = nullptr;
    if (!s2) {
        cudaStreamCreateWithFlags(&s2, cudaStreamNonBlocking);
        cudaEventCreateWithFlags(&evFork, cudaEventDisableTiming);
        cudaEventCreateWithFlags(&evJoin, cudaEventDisableTiming);
    }

    int nb = (n + 255) / 256;
    int eb = (E + 255) / 256;

    // fork: main = W-prep + GEMM; s2 = edge prep + CSR build
    cudaEventRecord(evFork, 0);
    cudaStreamWaitEvent(s2, evFork, 0);

    k_prep_w<<<64, 256>>>(w);
    int smem_bytes = (2 * 128 * SA_STRIDE + 256) * sizeof(float);
    cudaFuncSetAttribute(k_gemm_tf32, cudaFuncAttributeMaxDynamicSharedMemorySize, smem_bytes);
    k_gemm_tf32<<<(n + 127) / 128, 256, smem_bytes>>>(x, att, n);

    k_prep_e<<<nb, 256, 0, s2>>>(ei32, n, E);
    k_hist<<<eb, 256, 0, s2>>>(ei32, E);
    k_scan_all<<<1, 1024, 0, s2>>>(n);
    k_permute<<<eb, 256, 0, s2>>>(ei32, E);

    cudaEventRecord(evJoin, s2);
    cudaStreamWaitEvent(0, evJoin, 0);

    k_gather<<<(n * 32 + 255) / 256, 256>>>(out, bias, n);
}

// round 17
// speedup vs baseline: 1.7503x; 1.7503x over previous
#include <cuda_runtime.h>
#include <cuda_fp16.h>
#include <math_constants.h>

#define MAXN 100000
#define MAXE 720000
#define NH   8
#define HC   128

__device__ __half g_xwh[MAXN * HC];   // x @ W, fp16 for gather  [N, H*C]
__device__ float  g_atgt[MAXN * NH];
__device__ float  g_asrc[MAXN * NH];
__device__ float  g_wt[HC * HC];      // W^T, tf32-rounded bits, [n][k]
__device__ int    g_deg[MAXN];
__device__ int    g_start[MAXN];      // exclusive prefix; after permute = end
__device__ int    g_srcidx[MAXE];
__device__ int    g_bsum[512];
__device__ int    g_is64;

__device__ __forceinline__ unsigned cvt_tf32(float f) {
    unsigned r;
    asm("cvt.rna.tf32.f32 %0, %1;" : "=r"(r) : "f"(f));
    return r;
}

__device__ __forceinline__ int edge_at(const int* ei32, int idx, int shift) {
    return ei32[idx << shift];
}

// ---------------------------------------------------------------------------
// K_prepW (main stream): W^T tf32 precompute — feeds the GEMM.
// ---------------------------------------------------------------------------
__global__ void k_prep_w(const float* __restrict__ w) {
    int i = blockIdx.x * blockDim.x + threadIdx.x;   // 16384 threads
    int k = i >> 7, nn = i & 127;
    g_wt[nn * HC + k] = __uint_as_float(cvt_tf32(w[i]));
}

// ---------------------------------------------------------------------------
// K_prepE (stream 2): zero degrees + detect edge dtype — feeds hist.
// ---------------------------------------------------------------------------
__global__ void k_prep_e(const int* __restrict__ ei32, int n, int E) {
    int i = blockIdx.x * blockDim.x + threadIdx.x;
    if (i < n) g_deg[i] = 0;
    if (i == 0) {
        int m = E < 128 ? E : 128;
        int nz = 0;
        for (int j = 0; j < m; j++) nz |= ei32[2 * j + 1];
        g_is64 = (nz == 0) ? 1 : 0;
    }
}

// ---------------------------------------------------------------------------
// K1: tf32 tensor-core GEMM xw = x @ W (128x128 tile/block) + fused att dots.
// (R10 proven version — 64 accumulators/thread, no spills.)
// ---------------------------------------------------------------------------
#define SA_STRIDE 132
__global__ void __launch_bounds__(256) k_gemm_tf32(
        const float* __restrict__ x, const float* __restrict__ att, int n) {
    extern __shared__ float smem[];
    float* sA   = smem;
    float* sB   = smem + 128 * SA_STRIDE;
    float* sAtt = smem + 2 * 128 * SA_STRIDE;

    int tid  = threadIdx.x;
    int lane = tid & 31, warp = tid >> 5;
    int g = lane >> 2, t = lane & 3;
    int row0g = blockIdx.x * 128;

    sAtt[tid] = att[tid];

    const float4* wt4 = (const float4*)g_wt;
#pragma unroll
    for (int i = 0; i < 16; i++) {
        int idx = tid + i * 256;
        int nn = idx >> 5, k4 = (idx & 31) * 4;
        *(float4*)(sB + nn * SA_STRIDE + k4) = wt4[idx];
    }

    const float4* x4 = (const float4*)(x + (size_t)row0g * 128);
#pragma unroll
    for (int i = 0; i < 16; i++) {
        int idx = tid + i * 256;
        int r  = idx >> 5;
        int c4 = (idx & 31) * 4;
        float4 v = (row0g + r < n) ? x4[idx] : make_float4(0.f, 0.f, 0.f, 0.f);
        float4 c;
        c.x = __uint_as_float(cvt_tf32(v.x));
        c.y = __uint_as_float(cvt_tf32(v.y));
        c.z = __uint_as_float(cvt_tf32(v.z));
        c.w = __uint_as_float(cvt_tf32(v.w));
        *(float4*)(sA + r * SA_STRIDE + c4) = c;
    }
    __syncthreads();

    int rbase = warp * 16;
    const float* pa0 = sA + (rbase + g) * SA_STRIDE;
    const float* pa1 = sA + (rbase + g + 8) * SA_STRIDE;

    float acc[16][4];
#pragma unroll
    for (int nt = 0; nt < 16; nt++)
#pragma unroll
        for (int j = 0; j < 4; j++) acc[nt][j] = 0.f;

#pragma unroll
    for (int kt = 0; kt < 16; kt++) {
        int k0 = kt * 8;
        unsigned a0 = __float_as_uint(pa0[k0 + t]);
        unsigned a1 = __float_as_uint(pa1[k0 + t]);
        unsigned a2 = __float_as_uint(pa0[k0 + t + 4]);
        unsigned a3 = __float_as_uint(pa1[k0 + t + 4]);
#pragma unroll
        for (int nt = 0; nt < 16; nt++) {
            const float* pb = sB + (nt * 8 + g) * SA_STRIDE + k0;
            unsigned b0 = __float_as_uint(pb[t]);
            unsigned b1 = __float_as_uint(pb[t + 4]);
            asm volatile(
                "mma.sync.aligned.m16n8k8.row.col.f32.tf32.tf32.f32 "
                "{%0,%1,%2,%3}, {%4,%5,%6,%7}, {%8,%9}, {%0,%1,%2,%3};"
                : "+f"(acc[nt][0]), "+f"(acc[nt][1]), "+f"(acc[nt][2]), "+f"(acc[nt][3])
                : "r"(a0), "r"(a1), "r"(a2), "r"(a3), "r"(b0), "r"(b1));
        }
    }

    int row0 = row0g + rbase + g;
    int row1 = row0 + 8;
#pragma unroll
    for (int nt = 0; nt < 16; nt++) {
        int col = nt * 8 + 2 * t;
        if (row0 < n)
            *(__half2*)(g_xwh + (size_t)row0 * 128 + col) = __floats2half2_rn(acc[nt][0], acc[nt][1]);
        if (row1 < n)
            *(__half2*)(g_xwh + (size_t)row1 * 128 + col) = __floats2half2_rn(acc[nt][2], acc[nt][3]);
    }

#pragma unroll
    for (int h = 0; h < NH; h++) {
        float dt0 = 0.f, ds0 = 0.f, dt1 = 0.f, ds1 = 0.f;
#pragma unroll
        for (int j = 0; j < 2; j++) {
            int nt = 2 * h + j;
            int cw = j * 8 + 2 * t;
            float at0 = sAtt[h * 32 + cw],      at1 = sAtt[h * 32 + cw + 1];
            float as0 = sAtt[h * 32 + 16 + cw], as1 = sAtt[h * 32 + 16 + cw + 1];
            dt0 += acc[nt][0] * at0 + acc[nt][1] * at1;
            ds0 += acc[nt][0] * as0 + acc[nt][1] * as1;
            dt1 += acc[nt][2] * at0 + acc[nt][3] * at1;
            ds1 += acc[nt][2] * as0 + acc[nt][3] * as1;
        }
        dt0 += __shfl_xor_sync(0xffffffff, dt0, 1); dt0 += __shfl_xor_sync(0xffffffff, dt0, 2);
        ds0 += __shfl_xor_sync(0xffffffff, ds0, 1); ds0 += __shfl_xor_sync(0xffffffff, ds0, 2);
        dt1 += __shfl_xor_sync(0xffffffff, dt1, 1); dt1 += __shfl_xor_sync(0xffffffff, dt1, 2);
        ds1 += __shfl_xor_sync(0xffffffff, ds1, 1); ds1 += __shfl_xor_sync(0xffffffff, ds1, 2);
        if (t == 0) {
            if (row0 < n) { g_atgt[row0 * NH + h] = dt0; g_asrc[row0 * NH + h] = ds0; }
            if (row1 < n) { g_atgt[row1 * NH + h] = dt1; g_asrc[row1 * NH + h] = ds1; }
        }
    }
}

// ---------------------------------------------------------------------------
// CSR build: histogram (4 edges/thread, MLP=4) -> 3-phase scan -> permute
// ---------------------------------------------------------------------------
__global__ void k_hist(const int* __restrict__ ei32, int E) {
    int i0 = (blockIdx.x * blockDim.x + threadIdx.x) * 4;
    int sh = g_is64;
    int d0 = -1, d1 = -1, d2 = -1, d3 = -1;
    if (i0 + 0 < E) d0 = edge_at(ei32, E + i0 + 0, sh);
    if (i0 + 1 < E) d1 = edge_at(ei32, E + i0 + 1, sh);
    if (i0 + 2 < E) d2 = edge_at(ei32, E + i0 + 2, sh);
    if (i0 + 3 < E) d3 = edge_at(ei32, E + i0 + 3, sh);
    if (d0 >= 0) atomicAdd(&g_deg[d0], 1);
    if (d1 >= 0) atomicAdd(&g_deg[d1], 1);
    if (d2 >= 0) atomicAdd(&g_deg[d2], 1);
    if (d3 >= 0) atomicAdd(&g_deg[d3], 1);
}

__global__ void k_scan1(int n) {
    int i = blockIdx.x * 256 + threadIdx.x;
    int lane = threadIdx.x & 31, w = threadIdx.x >> 5;
    int v = (i < n) ? g_deg[i] : 0;
    int x = v;
#pragma unroll
    for (int o = 1; o < 32; o <<= 1) {
        int y = __shfl_up_sync(0xffffffff, x, o);
        if (lane >= o) x += y;
    }
    __shared__ int wsum[8];
    if (lane == 31) wsum[w] = x;
    __syncthreads();
    if (threadIdx.x < 8) {
        int s = wsum[threadIdx.x];
#pragma unroll
        for (int o = 1; o < 8; o <<= 1) {
            int y = __shfl_up_sync(0xff, s, o);
            if ((int)threadIdx.x >= o) s += y;
        }
        wsum[threadIdx.x] = s;
    }
    __syncthreads();
    int base = (w > 0) ? wsum[w - 1] : 0;
    if (i < n) g_start[i] = base + x - v;
    if (threadIdx.x == 0) g_bsum[blockIdx.x] = wsum[7];
}

__global__ void k_scan2(int nb) {
    int i = threadIdx.x;
    int lane = i & 31, w = i >> 5;
    int v = (i < nb) ? g_bsum[i] : 0;
    int x = v;
#pragma unroll
    for (int o = 1; o < 32; o <<= 1) {
        int y = __shfl_up_sync(0xffffffff, x, o);
        if (lane >= o) x += y;
    }
    __shared__ int wsum[16];
    if (lane == 31) wsum[w] = x;
    __syncthreads();
    if (i < 16) {
        int s = wsum[i];
#pragma unroll
        for (int o = 1; o < 16; o <<= 1) {
            int y = __shfl_up_sync(0xffff, s, o);
            if (i >= o) s += y;
        }
        wsum[i] = s;
    }
    __syncthreads();
    int base = (w > 0) ? wsum[w - 1] : 0;
    if (i < nb) g_bsum[i] = base + x - v;
}

__global__ void k_scan3(int n) {
    int i = blockIdx.x * 256 + threadIdx.x;
    if (i < n) g_start[i] += g_bsum[blockIdx.x];
}

__global__ void k_permute(const int* __restrict__ ei32, int E) {
    int i0 = (blockIdx.x * blockDim.x + threadIdx.x) * 4;
    int sh = g_is64;
#pragma unroll
    for (int j = 0; j < 4; j++) {
        int i = i0 + j;
        if (i < E) {
            int s = edge_at(ei32, i, sh);
            int d = edge_at(ei32, E + i, sh);
            int pos = atomicAdd(&g_start[d], 1);   // g_start becomes end-of-bucket
            g_srcidx[pos] = s;
        }
    }
}

// ---------------------------------------------------------------------------
// K5: gather — one warp per dst node, software-pipelined, fp16 xw.
// ---------------------------------------------------------------------------
__global__ void __launch_bounds__(256) k_gather(float* __restrict__ out,
                                                const float* __restrict__ bias, int n) {
    int gw = (blockIdx.x * blockDim.x + threadIdx.x) >> 5;
    if (gw >= n) return;
    int lane = threadIdx.x & 31;
    int d = gw;
    int h = lane >> 2;
    float atgtv = g_atgt[d * NH + h];
    int deg = g_deg[d];
    int start = g_start[d] - deg;          // g_start holds end after permute
    float4 acc = make_float4(0.f, 0.f, 0.f, 0.f);
    float den = 0.f;
    const uint2* xw2 = (const uint2*)g_xwh;

    if (deg > 0) {
        int s_n = g_srcidx[start];
        float as_n = g_asrc[s_n * NH + h];
        uint2 v_n = __ldg(xw2 + (size_t)s_n * 32 + lane);
        for (int j = 0; j < deg; j++) {
            float as = as_n;
            uint2 vr = v_n;
            if (j + 1 < deg) {
                int s2 = g_srcidx[start + j + 1];
                as_n = g_asrc[s2 * NH + h];
                v_n = __ldg(xw2 + (size_t)s2 * 32 + lane);
            }
            float a = atgtv + as;
            a = a > 0.f ? a : 0.2f * a;
            float ex = __expf(a);
            float2 lo = __half22float2(*(__half2*)&vr.x);
            float2 hi = __half22float2(*(__half2*)&vr.y);
            acc.x += ex * lo.x; acc.y += ex * lo.y;
            acc.z += ex * hi.x; acc.w += ex * hi.y;
            den += ex;
        }
    }
    float inv = (den > 0.f) ? 1.f / den : 0.f;
    float4 b = ((const float4*)bias)[lane];
    float4 o;
    o.x = acc.x * inv + b.x; o.y = acc.y * inv + b.y;
    o.z = acc.z * inv + b.z; o.w = acc.w * inv + b.w;
    ((float4*)out)[(size_t)d * 32 + lane] = o;
}

// ---------------------------------------------------------------------------
extern "C" void kernel_launch(void* const* d_in, const int* in_sizes, int n_in,
                              void* d_out, int out_size) {
    int order[16];
    for (int i = 0; i < n_in; i++) order[i] = i;
    for (int a = 0; a < n_in; a++)
        for (int b = a + 1; b < n_in; b++)
            if (in_sizes[order[b]] > in_sizes[order[a]]) {
                int t = order[a]; order[a] = order[b]; order[b] = t;
            }
    const float* x    = (const float*)d_in[order[0]];
    const int*   ei32 = (const int*)  d_in[order[1]];
    const float* w    = (const float*)d_in[order[3]];
    const float* att  = (const float*)d_in[order[4]];
    const float* bias = (const float*)d_in[order[5]];
    float*       out  = (float*)d_out;

    int n = in_sizes[order[0]] / 128;
    int E = in_sizes[order[1]] / 2;

    static cudaStream_t s2 = nullptr;
    static cudaEvent_t evFork = nullptr, evJoin = nullptr;
    if (!s2) {
        cudaStreamCreateWithFlags(&s2, cudaStreamNonBlocking);
        cudaEventCreateWithFlags(&evFork, cudaEventDisableTiming);
        cudaEventCreateWithFlags(&evJoin, cudaEventDisableTiming);
    }

    int nb = (n + 255) / 256;
    int eb4 = (E + 1023) / 1024;   // 4 edges per thread

    // fork: main = W-prep + GEMM; s2 = edge prep + CSR build
    cudaEventRecord(evFork, 0);
    cudaStreamWaitEvent(s2, evFork, 0);

    k_prep_w<<<64, 256>>>(w);
    int smem_bytes = (2 * 128 * SA_STRIDE + 256) * sizeof(float);
    cudaFuncSetAttribute(k_gemm_tf32, cudaFuncAttributeMaxDynamicSharedMemorySize, smem_bytes);
    k_gemm_tf32<<<(n + 127) / 128, 256, smem_bytes>>>(x, att, n);

    k_prep_e<<<nb, 256, 0, s2>>>(ei32, n, E);
    k_hist<<<eb4, 256, 0, s2>>>(ei32, E);
    k_scan1<<<nb, 256, 0, s2>>>(n);
    k_scan2<<<1, 512, 0, s2>>>(nb);
    k_scan3<<<nb, 256, 0, s2>>>(n);
    k_permute<<<eb4, 256, 0, s2>>>(ei32, E);

    cudaEventRecord(evJoin, s2);
    cudaStreamWaitEvent(0, evJoin, 0);

    k_gather<<<(n * 32 + 255) / 256, 256>>>(out, bias, n);
}